// round 9
// baseline (speedup 1.0000x reference)
#include <cuda_runtime.h>
#include <cuda_fp16.h>
#include <stdint.h>

// out[32768,256] = A[32768, K=2304] * Wt[K,256], fp16 operands, fp32 accum,
// ldmatrix + mma.sync.m16n8k16 (portable for compute_100).
//
// Warp-specialized: 8 consumer warps (pure ldmatrix+MMA, r4's 64x32 warp
// tile) + 4 producer warps (x load, silu+spline A-gen, B cp.async) over
// 2-stage A and B smem rings, synchronized with named barriers. No
// __syncthreads in the main loop -> the genA/copy chains that convoyed
// rounds 6-8 now overlap the MMA stream.
//
// K layout: k = 9*i + j; j=0: silu(x_i), j=1..8: cubic B-spline bases
// (closed-form, 4 nonzero). Chunk: 16 features = 144 k = 9 k16 steps.
// 304-B smem row stride (76 words -> ldmatrix conflict-free).

#define N_IN   256
#define KTOT   2304
#define CHUNKS 16
#define CK     144
#define KSTEPS 9
#define ROWB   304
#define STG    (128 * ROWB)            // 38912 per stage
#define DYN_SMEM (4 * STG)             // A0 A1 B0 B1 = 155648

#define BAR_FULL0  1
#define BAR_FULL1  2
#define BAR_EMPTY0 3
#define BAR_EMPTY1 4
#define NTHR 384

__device__ __align__(128) __half g_Wh[N_IN * KTOT];   // [out][k] fp16

// ---- helpers --------------------------------------------------------------
__device__ __forceinline__ uint32_t smem_u32(const void* p) {
    uint32_t a;
    asm("{ .reg .u64 t; cvta.to.shared.u64 t, %1; cvt.u32.u64 %0, t; }" : "=r"(a) : "l"(p));
    return a;
}
__device__ __forceinline__ void bar_sync(int id) {
    asm volatile("bar.sync %0, %1;" :: "r"(id), "n"(NTHR) : "memory");
}
__device__ __forceinline__ void bar_arrive(int id) {
    asm volatile("bar.arrive %0, %1;" :: "r"(id), "n"(NTHR) : "memory");
}
__device__ __forceinline__ void cp16(uint32_t dst, const void* src) {
    asm volatile("cp.async.cg.shared.global [%0], [%1], 16;" :: "r"(dst), "l"(src) : "memory");
}
__device__ __forceinline__ void cp_commit() {
    asm volatile("cp.async.commit_group;" ::: "memory");
}
template <int N>
__device__ __forceinline__ void cp_wait() {
    asm volatile("cp.async.wait_group %0;" :: "n"(N) : "memory");
}
__device__ __forceinline__ void ldm_x4(uint32_t& r0, uint32_t& r1, uint32_t& r2, uint32_t& r3,
                                       uint32_t addr) {
    asm volatile("ldmatrix.sync.aligned.m8n8.x4.shared.b16 {%0,%1,%2,%3}, [%4];"
                 : "=r"(r0), "=r"(r1), "=r"(r2), "=r"(r3) : "r"(addr));
}
__device__ __forceinline__ void mma16816(float& c0, float& c1, float& c2, float& c3,
                                         uint32_t a0, uint32_t a1, uint32_t a2, uint32_t a3,
                                         uint32_t b0, uint32_t b1) {
    asm volatile(
        "mma.sync.aligned.m16n8k16.row.col.f32.f16.f16.f32 "
        "{%0,%1,%2,%3}, {%4,%5,%6,%7}, {%8,%9}, {%0,%1,%2,%3};"
        : "+f"(c0), "+f"(c1), "+f"(c2), "+f"(c3)
        : "r"(a0), "r"(a1), "r"(a2), "r"(a3), "r"(b0), "r"(b1));
}

// ---- weight repack to fp16 [out][k] ---------------------------------------
__global__ void repack_kernel(const float* __restrict__ baseW,
                              const float* __restrict__ splineW) {
    int idx = blockIdx.x * blockDim.x + threadIdx.x;
    if (idx >= N_IN * KTOT) return;
    int o = idx / KTOT, k = idx % KTOT;
    int i = k / 9, j = k % 9;
    float v = (j == 0) ? baseW[o * N_IN + i] : splineW[o * (N_IN * 8) + i * 8 + (j - 1)];
    g_Wh[idx] = __float2half_rn(v);
}

// ---- main fused kernel ----------------------------------------------------
__global__ __launch_bounds__(NTHR, 1)
void kan_hmma_kernel(const float* __restrict__ x, float* __restrict__ out) {
    extern __shared__ __align__(128) unsigned char dsm[];   // A0 A1 B0 B1
    const uint32_t sb = smem_u32(dsm);
    const int tid = threadIdx.x, wid = tid >> 5, lane = tid & 31;
    const int row0 = blockIdx.x * 128;
    const int ct   = blockIdx.y;                 // output col tile (0/1)

    if (wid >= 8) {
        // ================= PRODUCER (4 warps, 128 threads) =================
        const int ptid = tid - 256;              // 0..127 -> row within tile
        const float* xrow = x + (size_t)(row0 + ptid) * N_IN;
        unsigned char* arow = dsm + (uint32_t)ptid * ROWB;  // stage 0 A row

        float4 xc[4], xn[4];
#pragma unroll
        for (int g = 0; g < 4; g++)
            xc[g] = *reinterpret_cast<const float4*>(xrow + g * 4);

        for (int c = 0; c < CHUNKS; c++) {
            const int buf = c & 1;
            // prefetch next chunk's x before any waiting
            if (c + 1 < CHUNKS)
#pragma unroll
                for (int g = 0; g < 4; g++)
                    xn[g] = *reinterpret_cast<const float4*>(xrow + (c + 1) * 16 + g * 4);

            if (c >= 2) bar_sync(BAR_EMPTY0 + buf);

            // ---- B stage via cp.async: 128 rows x 18 segs of 16B ----
            {
                const uint32_t bbyte = sb + (uint32_t)(2 + buf) * STG;
                const __half* src0 = g_Wh + (size_t)(ct * 128) * KTOT + c * CK;
#pragma unroll
                for (int s = 0; s < 18; s++) {
                    int e = ptid + 128 * s;      // 0..2303
                    int n = e / 18, seg = e % 18;
                    cp16(bbyte + (uint32_t)n * ROWB + seg * 16,
                         src0 + (size_t)n * KTOT + seg * 8);
                }
                cp_commit();
            }

            // ---- A gen: this thread's row, 16 features in 4 quads ----
            {
                unsigned char* dst = arow + (uint32_t)buf * STG;
#pragma unroll
                for (int g = 0; g < 4; g++) {
                    float xv[4] = {xc[g].x, xc[g].y, xc[g].z, xc[g].w};
                    uint32_t pk[18];
#pragma unroll
                    for (int ff = 0; ff < 4; ff++) {
                        float v = xv[ff];
                        float sil = v / (1.f + __expf(-v));
                        int j0 = (int)floorf(fmaf(v, 2.5f, 5.5f));
                        float gk = fmaf(0.4f, (float)j0, -2.2f);
                        float u = (v - gk) * 2.5f;
                        float u2 = u * u, u3 = u2 * u, omu = 1.f - u;
                        float w0 = omu * omu * omu * (1.f / 6.f);
                        float w1 = fmaf(0.5f, u3, fmaf(-1.f, u2, 2.f / 3.f));
                        float w2 = fmaf(-0.5f, u3, fmaf(0.5f, u2, fmaf(0.5f, u, 1.f / 6.f)));
                        float w3 = u3 * (1.f / 6.f);
                        unsigned short h0 = __half_as_ushort(__float2half_rn(w0));
                        unsigned short h1 = __half_as_ushort(__float2half_rn(w1));
                        unsigned short h2 = __half_as_ushort(__float2half_rn(w2));
                        unsigned short h3 = __half_as_ushort(__float2half_rn(w3));
                        unsigned short hh[9];
                        hh[0] = __half_as_ushort(__float2half_rn(sil));
#pragma unroll
                        for (int i = 0; i < 8; i++) {
                            int d = j0 - i;
                            unsigned short b = (d == 0) ? h3 : (d == 1) ? h2
                                             : (d == 2) ? h1 : (d == 3) ? h0
                                             : (unsigned short)0;
                            hh[i + 1] = b;
                        }
#pragma unroll
                        for (int j = 0; j < 9; j++) {
                            int pos = 9 * ff + j;
                            uint32_t word = (uint32_t)hh[j] << ((pos & 1) * 16);
                            if ((pos & 1) == 0) pk[pos >> 1] = word;
                            else                pk[pos >> 1] |= word;
                        }
                    }
#pragma unroll
                    for (int q = 0; q < 9; q++)
                        *reinterpret_cast<uint2*>(dst + g * 72 + q * 8) =
                            make_uint2(pk[2 * q], pk[2 * q + 1]);
                }
            }

            cp_wait<0>();                         // B stage landed
            __threadfence_block();                // STS visible before release
            bar_arrive(BAR_FULL0 + buf);

#pragma unroll
            for (int g = 0; g < 4; g++) xc[g] = xn[g];
        }
        return;                                   // producers exit
    }

    // =================== CONSUMER (8 warps, 256 threads) ===================
    // warp tiling: 2 (m-half) x 4 (n); warp tile 64 rows x 32 cols (r4)
    const int wm = wid & 1;
    const int wn = wid >> 1;
    const uint32_t a_off = (uint32_t)(wm * 64 + (lane & 15)) * ROWB + ((lane >> 4) << 3) * 2;
    const uint32_t b_off = (uint32_t)(wn * 32 + ((lane >> 4) << 3) + (lane & 7)) * ROWB
                         + (((lane >> 3) & 1) << 3) * 2;

    float C[4][4][4];                             // [mt][nt8][frag]
#pragma unroll
    for (int a = 0; a < 4; a++)
#pragma unroll
        for (int b = 0; b < 4; b++)
#pragma unroll
            for (int c = 0; c < 4; c++) C[a][b][c] = 0.f;

    for (int c = 0; c < CHUNKS; c++) {
        const int buf = c & 1;
        const uint32_t abase = sb + (uint32_t)buf * STG;
        const uint32_t bbase = sb + (uint32_t)(2 + buf) * STG;

        bar_sync(BAR_FULL0 + buf);                // stage filled by producers

#pragma unroll
        for (int s = 0; s < KSTEPS; s++) {
            const uint32_t kb = (uint32_t)(s * 16) * 2;
            uint32_t A[4][4], B[2][4];
#pragma unroll
            for (int mt = 0; mt < 4; mt++)
                ldm_x4(A[mt][0], A[mt][1], A[mt][2], A[mt][3],
                       abase + a_off + (uint32_t)mt * (16 * ROWB) + kb);
#pragma unroll
            for (int nt = 0; nt < 2; nt++)
                ldm_x4(B[nt][0], B[nt][1], B[nt][2], B[nt][3],
                       bbase + b_off + (uint32_t)nt * (16 * ROWB) + kb);
#pragma unroll
            for (int mt = 0; mt < 4; mt++)
#pragma unroll
                for (int nt = 0; nt < 2; nt++) {
                    mma16816(C[mt][2 * nt][0], C[mt][2 * nt][1],
                             C[mt][2 * nt][2], C[mt][2 * nt][3],
                             A[mt][0], A[mt][1], A[mt][2], A[mt][3],
                             B[nt][0], B[nt][1]);
                    mma16816(C[mt][2 * nt + 1][0], C[mt][2 * nt + 1][1],
                             C[mt][2 * nt + 1][2], C[mt][2 * nt + 1][3],
                             A[mt][0], A[mt][1], A[mt][2], A[mt][3],
                             B[nt][2], B[nt][3]);
                }
        }

        bar_arrive(BAR_EMPTY0 + buf);             // stage free for refill
    }

    // ---- epilogue: C frags -> gmem (r4 mapping) ----
    const int crow = lane >> 2, ccol = (lane & 3) * 2;
#pragma unroll
    for (int mt = 0; mt < 4; mt++) {
        int r = row0 + wm * 64 + mt * 16 + crow;
#pragma unroll
        for (int nt8 = 0; nt8 < 4; nt8++) {
            int cc = ct * 128 + wn * 32 + nt8 * 8 + ccol;
            *reinterpret_cast<float2*>(out + (size_t)r * 256 + cc) =
                make_float2(C[mt][nt8][0], C[mt][nt8][1]);
            *reinterpret_cast<float2*>(out + (size_t)(r + 8) * 256 + cc) =
                make_float2(C[mt][nt8][2], C[mt][nt8][3]);
        }
    }
}

// ---- launch ---------------------------------------------------------------
extern "C" void kernel_launch(void* const* d_in, const int* in_sizes, int n_in,
                              void* d_out, int out_size) {
    const float* x       = (const float*)d_in[0];
    const float* baseW   = (const float*)d_in[1];
    const float* splineW = (const float*)d_in[2];
    float* out           = (float*)d_out;
    const int n_rows = in_sizes[0] / N_IN;            // 32768

    repack_kernel<<<(N_IN * KTOT + 255) / 256, 256>>>(baseW, splineW);

    cudaFuncSetAttribute(kan_hmma_kernel, cudaFuncAttributeMaxDynamicSharedMemorySize, DYN_SMEM);
    dim3 grid(n_rows / 128, 2);
    kan_hmma_kernel<<<grid, NTHR, DYN_SMEM>>>(x, out);
}

// round 10
// speedup vs baseline: 1.6512x; 1.6512x over previous
#include <cuda_runtime.h>
#include <cuda_fp16.h>
#include <stdint.h>

// out[32768,256] = A[32768, K=2304] * Wt[K,256], fp16 operands, fp32 accum,
// ldmatrix + mma.sync.m16n8k16 (portable for compute_100).
//
// This is round-4's exact 301us structure (128x128 CTA tile, 256 threads,
// 8 warps of 64x32 warp tiles, A/B double-buffered, uint4 A stores) with
// exactly ONE functional change: genA uses the closed-form cubic B-spline
// (4 nonzero bases, select-chain placement) instead of the Cox-de-Boor
// recursion, plus next-chunk x prefetched into registers.
//
// K layout: k = 9*i + j; j=0: silu(x_i), j=1..8: bases. Chunk: 16 features
// = 144 k = 9 k16 steps. 304-B smem row stride (conflict-free ldmatrix/STS).

#define N_IN   256
#define KTOT   2304
#define CHUNKS 16
#define CK     144
#define KSTEPS 9
#define ROWB   304
#define TBUF   (128 * ROWB)   // 38912
#define DYN_SMEM (4 * TBUF)   // A0 A1 B0 B1 = 155648

__device__ __align__(128) __half g_Wh[N_IN * KTOT];   // [out][k] fp16

// ---- helpers --------------------------------------------------------------
__device__ __forceinline__ uint32_t smem_u32(const void* p) {
    uint32_t a;
    asm("{ .reg .u64 t; cvta.to.shared.u64 t, %1; cvt.u32.u64 %0, t; }" : "=r"(a) : "l"(p));
    return a;
}
__device__ __forceinline__ void cp16(uint32_t dst, const void* src) {
    asm volatile("cp.async.cg.shared.global [%0], [%1], 16;" :: "r"(dst), "l"(src) : "memory");
}
__device__ __forceinline__ void cp_commit() {
    asm volatile("cp.async.commit_group;" ::: "memory");
}
template <int N>
__device__ __forceinline__ void cp_wait() {
    asm volatile("cp.async.wait_group %0;" :: "n"(N) : "memory");
}
__device__ __forceinline__ void ldm_x4(uint32_t& r0, uint32_t& r1, uint32_t& r2, uint32_t& r3,
                                       uint32_t addr) {
    asm volatile("ldmatrix.sync.aligned.m8n8.x4.shared.b16 {%0,%1,%2,%3}, [%4];"
                 : "=r"(r0), "=r"(r1), "=r"(r2), "=r"(r3) : "r"(addr));
}
__device__ __forceinline__ void mma16816(float& c0, float& c1, float& c2, float& c3,
                                         uint32_t a0, uint32_t a1, uint32_t a2, uint32_t a3,
                                         uint32_t b0, uint32_t b1) {
    asm volatile(
        "mma.sync.aligned.m16n8k16.row.col.f32.f16.f16.f32 "
        "{%0,%1,%2,%3}, {%4,%5,%6,%7}, {%8,%9}, {%0,%1,%2,%3};"
        : "+f"(c0), "+f"(c1), "+f"(c2), "+f"(c3)
        : "r"(a0), "r"(a1), "r"(a2), "r"(a3), "r"(b0), "r"(b1));
}

// ---- weight repack to fp16 [out][k] ---------------------------------------
__global__ void repack_kernel(const float* __restrict__ baseW,
                              const float* __restrict__ splineW) {
    int idx = blockIdx.x * blockDim.x + threadIdx.x;
    if (idx >= N_IN * KTOT) return;
    int o = idx / KTOT, k = idx % KTOT;
    int i = k / 9, j = k % 9;
    float v = (j == 0) ? baseW[o * N_IN + i] : splineW[o * (N_IN * 8) + i * 8 + (j - 1)];
    g_Wh[idx] = __float2half_rn(v);
}

// ---- main fused kernel ----------------------------------------------------
__global__ __launch_bounds__(256, 1)
void kan_hmma_kernel(const float* __restrict__ x, float* __restrict__ out) {
    extern __shared__ __align__(128) unsigned char dsm[];   // A0 A1 B0 B1
    const uint32_t sb = smem_u32(dsm);
    const int tid = threadIdx.x, wid = tid >> 5, lane = tid & 31;
    const int row0 = blockIdx.x * 128;
    const int ct   = blockIdx.y;              // output col tile (0/1)

    // A generation mapping: thread -> (row = tid>>1, feature-half = tid&1)
    const int grow = tid >> 1;
    const int gfh  = tid & 1;                 // features 8*gfh..8*gfh+7
    const float* xrow = x + (size_t)(row0 + grow) * N_IN;

    // warp tiling: 2 (m) x 4 (n); warp tile 64 rows x 32 cols (r4)
    const int wm = wid & 1;
    const int wn = wid >> 1;

    const uint32_t a_off = (uint32_t)(wm * 64 + (lane & 15)) * ROWB + ((lane >> 4) << 3) * 2;
    const uint32_t b_off = (uint32_t)(wn * 32 + ((lane >> 4) << 3) + (lane & 7)) * ROWB
                         + (((lane >> 3) & 1) << 3) * 2;

    float C[4][4][4];                          // [mt][nt8][frag]
#pragma unroll
    for (int a = 0; a < 4; a++)
#pragma unroll
        for (int b = 0; b < 4; b++)
#pragma unroll
            for (int c = 0; c < 4; c++) C[a][b][c] = 0.f;

    // ---- A generator: closed-form spline, 8 features from 2 float4s ----
    auto genA = [&](float4 xa, float4 xb, uint32_t abyte) {
        float xv[8] = {xa.x, xa.y, xa.z, xa.w, xb.x, xb.y, xb.z, xb.w};
        uint32_t pk[36];
#pragma unroll
        for (int f = 0; f < 8; f++) {
            float v = xv[f];
            float sil = v / (1.f + __expf(-v));
            int j0 = (int)floorf(fmaf(v, 2.5f, 5.5f));
            float g = fmaf(0.4f, (float)j0, -2.2f);
            float u = (v - g) * 2.5f;
            float u2 = u * u, u3 = u2 * u, omu = 1.f - u;
            float w0 = omu * omu * omu * (1.f / 6.f);
            float w1 = fmaf(0.5f, u3, fmaf(-1.f, u2, 2.f / 3.f));
            float w2 = fmaf(-0.5f, u3, fmaf(0.5f, u2, fmaf(0.5f, u, 1.f / 6.f)));
            float w3 = u3 * (1.f / 6.f);
            unsigned short h0 = __half_as_ushort(__float2half_rn(w0));
            unsigned short h1 = __half_as_ushort(__float2half_rn(w1));
            unsigned short h2 = __half_as_ushort(__float2half_rn(w2));
            unsigned short h3 = __half_as_ushort(__float2half_rn(w3));
            unsigned short hh[9];
            hh[0] = __half_as_ushort(__float2half_rn(sil));
#pragma unroll
            for (int i = 0; i < 8; i++) {
                int d = j0 - i;
                unsigned short b = (d == 0) ? h3 : (d == 1) ? h2
                                 : (d == 2) ? h1 : (d == 3) ? h0 : (unsigned short)0;
                hh[i + 1] = b;
            }
#pragma unroll
            for (int j = 0; j < 9; j++) {
                int pos = 9 * f + j;
                uint32_t word = (uint32_t)hh[j] << ((pos & 1) * 16);
                if ((pos & 1) == 0) pk[pos >> 1] = word;
                else                pk[pos >> 1] |= word;
            }
        }
        unsigned char* dst = dsm + abyte + (uint32_t)grow * ROWB + (uint32_t)gfh * 144;
#pragma unroll
        for (int q = 0; q < 9; q++) {
            uint4 v = make_uint4(pk[4 * q], pk[4 * q + 1], pk[4 * q + 2], pk[4 * q + 3]);
            *reinterpret_cast<uint4*>(dst + q * 16) = v;
        }
    };

    // ---- B stage via cp.async: 128 rows x 18 segs of 16B ----
    auto issueB = [&](int c, uint32_t bbyte) {
        const __half* src0 = g_Wh + (size_t)(ct * 128) * KTOT + c * CK;
#pragma unroll
        for (int s = 0; s < 9; s++) {
            int e = tid + 256 * s;            // 0..2303
            int n = e / 18, seg = e % 18;
            cp16(sb + bbyte + (uint32_t)n * ROWB + seg * 16,
                 src0 + (size_t)n * KTOT + seg * 8);
        }
        cp_commit();
    };

    // ---- prologue ----
    {
        float4 xa = *reinterpret_cast<const float4*>(xrow + gfh * 8);
        float4 xb = *reinterpret_cast<const float4*>(xrow + gfh * 8 + 4);
        genA(xa, xb, 0);
    }
    issueB(0, 2 * TBUF);
    issueB(1, 3 * TBUF);
    cp_wait<1>();
    __syncthreads();

    // ---- main loop ----
    for (int c = 0; c < CHUNKS; c++) {
        const int buf = c & 1;
        const uint32_t abase = sb + (uint32_t)buf * TBUF;
        const uint32_t bbase = sb + (uint32_t)(2 + buf) * TBUF;

        // prefetch next chunk's x before the MMA block (hides LDG latency)
        float4 xa, xb;
        if (c + 1 < CHUNKS) {
            xa = *reinterpret_cast<const float4*>(xrow + (c + 1) * 16 + gfh * 8);
            xb = *reinterpret_cast<const float4*>(xrow + (c + 1) * 16 + gfh * 8 + 4);
        }

#pragma unroll
        for (int s = 0; s < KSTEPS; s++) {
            const uint32_t kb = (uint32_t)(s * 16) * 2;
            uint32_t A[4][4], B[2][4];
#pragma unroll
            for (int mt = 0; mt < 4; mt++)
                ldm_x4(A[mt][0], A[mt][1], A[mt][2], A[mt][3],
                       abase + a_off + (uint32_t)mt * (16 * ROWB) + kb);
#pragma unroll
            for (int nt = 0; nt < 2; nt++)
                ldm_x4(B[nt][0], B[nt][1], B[nt][2], B[nt][3],
                       bbase + b_off + (uint32_t)nt * (16 * ROWB) + kb);
#pragma unroll
            for (int mt = 0; mt < 4; mt++)
#pragma unroll
                for (int nt = 0; nt < 2; nt++) {
                    mma16816(C[mt][2 * nt][0], C[mt][2 * nt][1],
                             C[mt][2 * nt][2], C[mt][2 * nt][3],
                             A[mt][0], A[mt][1], A[mt][2], A[mt][3],
                             B[nt][0], B[nt][1]);
                    mma16816(C[mt][2 * nt + 1][0], C[mt][2 * nt + 1][1],
                             C[mt][2 * nt + 1][2], C[mt][2 * nt + 1][3],
                             A[mt][0], A[mt][1], A[mt][2], A[mt][3],
                             B[nt][2], B[nt][3]);
                }
        }

        if (c + 1 < CHUNKS) genA(xa, xb, (uint32_t)(buf ^ 1) * TBUF);
        __syncthreads();
        if (c + 2 < CHUNKS) {
            issueB(c + 2, (uint32_t)(2 + buf) * TBUF);
            cp_wait<1>();
        } else {
            cp_wait<0>();
        }
        __syncthreads();
    }

    // ---- epilogue: C frags -> gmem ----
    const int crow = lane >> 2, ccol = (lane & 3) * 2;
#pragma unroll
    for (int mt = 0; mt < 4; mt++) {
        int r = row0 + wm * 64 + mt * 16 + crow;
#pragma unroll
        for (int nt8 = 0; nt8 < 4; nt8++) {
            int cc = ct * 128 + wn * 32 + nt8 * 8 + ccol;
            *reinterpret_cast<float2*>(out + (size_t)r * 256 + cc) =
                make_float2(C[mt][nt8][0], C[mt][nt8][1]);
            *reinterpret_cast<float2*>(out + (size_t)(r + 8) * 256 + cc) =
                make_float2(C[mt][nt8][2], C[mt][nt8][3]);
        }
    }
}

// ---- launch ---------------------------------------------------------------
extern "C" void kernel_launch(void* const* d_in, const int* in_sizes, int n_in,
                              void* d_out, int out_size) {
    const float* x       = (const float*)d_in[0];
    const float* baseW   = (const float*)d_in[1];
    const float* splineW = (const float*)d_in[2];
    float* out           = (float*)d_out;
    const int n_rows = in_sizes[0] / N_IN;            // 32768

    repack_kernel<<<(N_IN * KTOT + 255) / 256, 256>>>(baseW, splineW);

    cudaFuncSetAttribute(kan_hmma_kernel, cudaFuncAttributeMaxDynamicSharedMemorySize, DYN_SMEM);
    dim3 grid(n_rows / 128, 2);
    kan_hmma_kernel<<<grid, 256, DYN_SMEM>>>(x, out);
}

// round 11
// speedup vs baseline: 4.3040x; 2.6067x over previous
#include <cuda_runtime.h>
#include <cuda_fp16.h>
#include <stdint.h>

// out[32768,256] = A[32768, K=2304] * Wt[K,256], fp16 operands, fp32 accum,
// via ldmatrix + mma.sync.m16n8k16 (portable: compiles for compute_100).
//
// Round-4's 301us kernel (recursion genA = ILP-rich latency filler; closed
// form measured 1.5-2.7x SLOWER in r6-r10) with ONE change: the 9 k16-steps
// are software-pipelined -- ldmatrix fragments for step s+1 issue before the
// MMAs of step s, breaking the ldmatrix->HMMA short-scoreboard stall.
//
// K layout: k = 9*i + j; j=0: silu(x_i), j=1..8: cubic B-spline bases.
// CTA tile: 128 rows x 128 outs. Chunk: 16 features = 144 k = 9 k16 steps.
// 304-byte smem row stride (76 words, 12 mod 32 -> conflict-free).

#define N_IN   256
#define KTOT   2304
#define CHUNKS 16
#define CK     144
#define KSTEPS 9
#define ROWB   304
#define TBUF   (128 * ROWB) // 38912
#define DYN_SMEM (4 * TBUF) // A0,A1,B0,B1 = 155648

__device__ __align__(128) __half g_Wh[N_IN * KTOT];   // [out][k] fp16

// ---- helpers --------------------------------------------------------------
__device__ __forceinline__ uint32_t smem_u32(const void* p) {
    uint32_t a;
    asm("{ .reg .u64 t; cvta.to.shared.u64 t, %1; cvt.u32.u64 %0, t; }" : "=r"(a) : "l"(p));
    return a;
}
__device__ __forceinline__ void cp16(uint32_t dst, const void* src) {
    asm volatile("cp.async.cg.shared.global [%0], [%1], 16;" :: "r"(dst), "l"(src) : "memory");
}
__device__ __forceinline__ void cp_commit() {
    asm volatile("cp.async.commit_group;" ::: "memory");
}
template <int N>
__device__ __forceinline__ void cp_wait() {
    asm volatile("cp.async.wait_group %0;" :: "n"(N) : "memory");
}
__device__ __forceinline__ void ldm_x4(uint32_t& r0, uint32_t& r1, uint32_t& r2, uint32_t& r3,
                                       uint32_t addr) {
    asm volatile("ldmatrix.sync.aligned.m8n8.x4.shared.b16 {%0,%1,%2,%3}, [%4];"
                 : "=r"(r0), "=r"(r1), "=r"(r2), "=r"(r3) : "r"(addr));
}
__device__ __forceinline__ void mma16816(float& c0, float& c1, float& c2, float& c3,
                                         uint32_t a0, uint32_t a1, uint32_t a2, uint32_t a3,
                                         uint32_t b0, uint32_t b1) {
    asm volatile(
        "mma.sync.aligned.m16n8k16.row.col.f32.f16.f16.f32 "
        "{%0,%1,%2,%3}, {%4,%5,%6,%7}, {%8,%9}, {%0,%1,%2,%3};"
        : "+f"(c0), "+f"(c1), "+f"(c2), "+f"(c3)
        : "r"(a0), "r"(a1), "r"(a2), "r"(a3), "r"(b0), "r"(b1));
}

// ---- cubic B-spline bases on grid -2.2 + 0.4j (Cox-de-Boor; ILP-rich) -----
__device__ __forceinline__ void compute_bases(float x, float b[8]) {
    const float h = 0.4f;
    float t[11];
#pragma unroll
    for (int i = 0; i < 11; i++) {
        float gl = -2.2f + i * h;
        t[i] = (x >= gl && x < gl + h) ? 1.0f : 0.0f;
    }
#pragma unroll
    for (int i = 0; i < 10; i++) {
        float gi = -2.2f + i * h;
        t[i] = (x - gi) * 2.5f * t[i] + ((gi + 2.f * h) - x) * 2.5f * t[i + 1];
    }
#pragma unroll
    for (int i = 0; i < 9; i++) {
        float gi = -2.2f + i * h;
        t[i] = (x - gi) * 1.25f * t[i] + ((gi + 3.f * h) - x) * 1.25f * t[i + 1];
    }
#pragma unroll
    for (int i = 0; i < 8; i++) {
        float gi = -2.2f + i * h;
        b[i] = (x - gi) * (2.5f / 3.f) * t[i] + ((gi + 4.f * h) - x) * (2.5f / 3.f) * t[i + 1];
    }
}

// ---- weight repack to fp16 [out][k] ---------------------------------------
__global__ void repack_kernel(const float* __restrict__ baseW,
                              const float* __restrict__ splineW) {
    int idx = blockIdx.x * blockDim.x + threadIdx.x;
    if (idx >= N_IN * KTOT) return;
    int o = idx / KTOT, k = idx % KTOT;
    int i = k / 9, j = k % 9;
    float v = (j == 0) ? baseW[o * N_IN + i] : splineW[o * (N_IN * 8) + i * 8 + (j - 1)];
    g_Wh[idx] = __float2half_rn(v);
}

// ---- main fused kernel ----------------------------------------------------
__global__ __launch_bounds__(256, 1)
void kan_hmma_kernel(const float* __restrict__ x, float* __restrict__ out) {
    extern __shared__ __align__(128) unsigned char dsm[];   // A0 A1 B0 B1
    const uint32_t sb = smem_u32(dsm);
    const int tid = threadIdx.x, wid = tid >> 5, lane = tid & 31;
    const int row0 = blockIdx.x * 128;
    const int ct   = blockIdx.y;              // output col tile (0/1)

    // A generation mapping: thread -> (row, feature-half)
    const int grow = tid & 127;               // 0..127
    const int gfh  = tid >> 7;                // 0/1 -> features 8*gfh..8*gfh+7
    const float* xrow = x + (size_t)(row0 + grow) * N_IN;

    // warp tiling: 2 (m) x 4 (n); warp tile 64 rows x 32 cols
    const int wm = wid & 1;
    const int wn = wid >> 1;

    const uint32_t a_off = (uint32_t)(wm * 64 + (lane & 15)) * ROWB + ((lane >> 4) << 3) * 2;
    const uint32_t b_off = (uint32_t)(wn * 32 + ((lane >> 4) << 3) + (lane & 7)) * ROWB
                         + (((lane >> 3) & 1) << 3) * 2;

    float C[4][4][4];                          // [mt][nt8][frag]
#pragma unroll
    for (int a = 0; a < 4; a++)
#pragma unroll
        for (int b = 0; b < 4; b++)
#pragma unroll
            for (int c = 0; c < 4; c++) C[a][b][c] = 0.f;

    // ---- A generator (chunk c -> buffer base byte offset within dsm) ----
    auto genA = [&](int c, uint32_t abyte) {
        float4 xa = *reinterpret_cast<const float4*>(xrow + c * 16 + gfh * 8);
        float4 xb = *reinterpret_cast<const float4*>(xrow + c * 16 + gfh * 8 + 4);
        float xv[8] = {xa.x, xa.y, xa.z, xa.w, xb.x, xb.y, xb.z, xb.w};
        uint32_t pk[36];
#pragma unroll
        for (int i = 0; i < 36; i++) pk[i] = 0u;
#pragma unroll
        for (int f = 0; f < 8; f++) {
            float v = xv[f];
            float sil = v / (1.f + __expf(-v));
            float bs[8];
            compute_bases(v, bs);
            unsigned short hh[9];
            hh[0] = __half_as_ushort(__float2half_rn(sil));
#pragma unroll
            for (int j = 0; j < 8; j++) hh[j + 1] = __half_as_ushort(__float2half_rn(bs[j]));
#pragma unroll
            for (int j = 0; j < 9; j++) {
                int pos = 9 * f + j;
                pk[pos >> 1] |= (uint32_t)hh[j] << ((pos & 1) * 16);
            }
        }
        unsigned char* dst = dsm + abyte + (uint32_t)grow * ROWB + (uint32_t)gfh * 144;
#pragma unroll
        for (int q = 0; q < 9; q++) {
            uint4 v = make_uint4(pk[4 * q], pk[4 * q + 1], pk[4 * q + 2], pk[4 * q + 3]);
            *reinterpret_cast<uint4*>(dst + q * 16) = v;
        }
    };

    // ---- B stage via cp.async: 128 rows x 18 segs of 16B ----
    auto issueB = [&](int c, uint32_t bbyte) {
        const __half* src0 = g_Wh + (size_t)(ct * 128) * KTOT + c * CK;
#pragma unroll
        for (int s = 0; s < 9; s++) {
            int e = tid + 256 * s;            // 0..2303
            int n = e / 18, seg = e % 18;
            cp16(sb + bbyte + (uint32_t)n * ROWB + seg * 16,
                 src0 + (size_t)n * KTOT + seg * 8);
        }
        cp_commit();
    };

    // ---- prologue ----
    genA(0, 0);
    issueB(0, 2 * TBUF);
    issueB(1, 3 * TBUF);
    cp_wait<1>();
    __syncthreads();

    // ---- main loop (k-steps software-pipelined) ----
    for (int c = 0; c < CHUNKS; c++) {
        const int buf = c & 1;
        const uint32_t abase = sb + (uint32_t)buf * TBUF;
        const uint32_t bbase = sb + (uint32_t)(2 + buf) * TBUF;

        uint32_t A[2][4][4], B[2][2][4];      // fragment double buffer

        // preload k-step 0 into set 0
#pragma unroll
        for (int mt = 0; mt < 4; mt++)
            ldm_x4(A[0][mt][0], A[0][mt][1], A[0][mt][2], A[0][mt][3],
                   abase + a_off + (uint32_t)mt * (16 * ROWB));
#pragma unroll
        for (int nt = 0; nt < 2; nt++)
            ldm_x4(B[0][nt][0], B[0][nt][1], B[0][nt][2], B[0][nt][3],
                   bbase + b_off + (uint32_t)nt * (16 * ROWB));

#pragma unroll
        for (int s = 0; s < KSTEPS; s++) {
            const int cur = s & 1, nxt = cur ^ 1;
            if (s + 1 < KSTEPS) {
                const uint32_t kb = (uint32_t)((s + 1) * 16) * 2;
#pragma unroll
                for (int mt = 0; mt < 4; mt++)
                    ldm_x4(A[nxt][mt][0], A[nxt][mt][1], A[nxt][mt][2], A[nxt][mt][3],
                           abase + a_off + (uint32_t)mt * (16 * ROWB) + kb);
#pragma unroll
                for (int nt = 0; nt < 2; nt++)
                    ldm_x4(B[nxt][nt][0], B[nxt][nt][1], B[nxt][nt][2], B[nxt][nt][3],
                           bbase + b_off + (uint32_t)nt * (16 * ROWB) + kb);
            }
#pragma unroll
            for (int mt = 0; mt < 4; mt++)
#pragma unroll
                for (int nt = 0; nt < 2; nt++) {
                    mma16816(C[mt][2 * nt][0], C[mt][2 * nt][1],
                             C[mt][2 * nt][2], C[mt][2 * nt][3],
                             A[cur][mt][0], A[cur][mt][1], A[cur][mt][2], A[cur][mt][3],
                             B[cur][nt][0], B[cur][nt][1]);
                    mma16816(C[mt][2 * nt + 1][0], C[mt][2 * nt + 1][1],
                             C[mt][2 * nt + 1][2], C[mt][2 * nt + 1][3],
                             A[cur][mt][0], A[cur][mt][1], A[cur][mt][2], A[cur][mt][3],
                             B[cur][nt][2], B[cur][nt][3]);
                }
        }

        if (c + 1 < CHUNKS) genA(c + 1, (uint32_t)(buf ^ 1) * TBUF);
        __syncthreads();
        if (c + 2 < CHUNKS) {
            issueB(c + 2, (uint32_t)(2 + buf) * TBUF);
            cp_wait<1>();
        } else {
            cp_wait<0>();
        }
        __syncthreads();
    }

    // ---- epilogue: C frags -> gmem ----
    const int crow = lane >> 2, ccol = (lane & 3) * 2;
#pragma unroll
    for (int mt = 0; mt < 4; mt++) {
        int r = row0 + wm * 64 + mt * 16 + crow;
#pragma unroll
        for (int nt8 = 0; nt8 < 4; nt8++) {
            int cc = ct * 128 + wn * 32 + nt8 * 8 + ccol;
            *reinterpret_cast<float2*>(out + (size_t)r * 256 + cc) =
                make_float2(C[mt][nt8][0], C[mt][nt8][1]);
            *reinterpret_cast<float2*>(out + (size_t)(r + 8) * 256 + cc) =
                make_float2(C[mt][nt8][2], C[mt][nt8][3]);
        }
    }
}

// ---- launch ---------------------------------------------------------------
extern "C" void kernel_launch(void* const* d_in, const int* in_sizes, int n_in,
                              void* d_out, int out_size) {
    const float* x       = (const float*)d_in[0];
    const float* baseW   = (const float*)d_in[1];
    const float* splineW = (const float*)d_in[2];
    float* out           = (float*)d_out;
    const int n_rows = in_sizes[0] / N_IN;            // 32768

    repack_kernel<<<(N_IN * KTOT + 255) / 256, 256>>>(baseW, splineW);

    cudaFuncSetAttribute(kan_hmma_kernel, cudaFuncAttributeMaxDynamicSharedMemorySize, DYN_SMEM);
    dim3 grid(n_rows / 128, 2);
    kan_hmma_kernel<<<grid, 256, DYN_SMEM>>>(x, out);
}

// round 12
// speedup vs baseline: 5.6211x; 1.3060x over previous
#include <cuda_runtime.h>
#include <cuda_fp16.h>
#include <stdint.h>

// Two-kernel split:
//  1) gen_kernel: x -> A fp16 [32768, 2304] in gmem (silu + Cox-de-Boor
//     bases; pure elementwise, full-chip occupancy, no tensor dependency).
//  2) gemm_kernel: out = A * Wt^T, a pure double-buffered cp.async + ldmatrix
//     + mma.sync.m16n8k16 GEMM (no fma in the main loop -> no phase convoy).
// Rounds 4-11 showed the fused kernel alternates tensor/fma phases inside one
// barrier convoy (duration = sum of phases). Splitting makes each kernel run
// its own pipe at full width.
//
// K layout: k = 9*i + j; j=0: silu(x_i), j=1..8: cubic B-spline bases.
// GEMM: CTA 128x128, 256 thr, 8 warps of 64x32 tiles, chunk 144 k (9 k16),
// 304-B smem row stride (76 words, 12 mod 32 -> conflict-free).

#define N_IN   256
#define KTOT   2304
#define CHUNKS 16
#define CK     144
#define KSTEPS 9
#define ROWB   304
#define TBUF   (128 * ROWB)   // 38912
#define DYN_SMEM (4 * TBUF)   // A0 A1 B0 B1 = 155648
#define NROWS  32768

__device__ __align__(128) __half g_Wh[N_IN * KTOT];          // [out][k]
__device__ __align__(128) __half g_A[(size_t)NROWS * KTOT];  // [row][k] scratch

// ---- helpers --------------------------------------------------------------
__device__ __forceinline__ uint32_t smem_u32(const void* p) {
    uint32_t a;
    asm("{ .reg .u64 t; cvta.to.shared.u64 t, %1; cvt.u32.u64 %0, t; }" : "=r"(a) : "l"(p));
    return a;
}
__device__ __forceinline__ void cp16(uint32_t dst, const void* src) {
    asm volatile("cp.async.cg.shared.global [%0], [%1], 16;" :: "r"(dst), "l"(src) : "memory");
}
__device__ __forceinline__ void cp_commit() {
    asm volatile("cp.async.commit_group;" ::: "memory");
}
template <int N>
__device__ __forceinline__ void cp_wait() {
    asm volatile("cp.async.wait_group %0;" :: "n"(N) : "memory");
}
__device__ __forceinline__ void ldm_x4(uint32_t& r0, uint32_t& r1, uint32_t& r2, uint32_t& r3,
                                       uint32_t addr) {
    asm volatile("ldmatrix.sync.aligned.m8n8.x4.shared.b16 {%0,%1,%2,%3}, [%4];"
                 : "=r"(r0), "=r"(r1), "=r"(r2), "=r"(r3) : "r"(addr));
}
__device__ __forceinline__ void mma16816(float& c0, float& c1, float& c2, float& c3,
                                         uint32_t a0, uint32_t a1, uint32_t a2, uint32_t a3,
                                         uint32_t b0, uint32_t b1) {
    asm volatile(
        "mma.sync.aligned.m16n8k16.row.col.f32.f16.f16.f32 "
        "{%0,%1,%2,%3}, {%4,%5,%6,%7}, {%8,%9}, {%0,%1,%2,%3};"
        : "+f"(c0), "+f"(c1), "+f"(c2), "+f"(c3)
        : "r"(a0), "r"(a1), "r"(a2), "r"(a3), "r"(b0), "r"(b1));
}

// ---- cubic B-spline bases on grid -2.2 + 0.4j (Cox-de-Boor) ---------------
__device__ __forceinline__ void compute_bases(float x, float b[8]) {
    const float h = 0.4f;
    float t[11];
#pragma unroll
    for (int i = 0; i < 11; i++) {
        float gl = -2.2f + i * h;
        t[i] = (x >= gl && x < gl + h) ? 1.0f : 0.0f;
    }
#pragma unroll
    for (int i = 0; i < 10; i++) {
        float gi = -2.2f + i * h;
        t[i] = (x - gi) * 2.5f * t[i] + ((gi + 2.f * h) - x) * 2.5f * t[i + 1];
    }
#pragma unroll
    for (int i = 0; i < 9; i++) {
        float gi = -2.2f + i * h;
        t[i] = (x - gi) * 1.25f * t[i] + ((gi + 3.f * h) - x) * 1.25f * t[i + 1];
    }
#pragma unroll
    for (int i = 0; i < 8; i++) {
        float gi = -2.2f + i * h;
        b[i] = (x - gi) * (2.5f / 3.f) * t[i] + ((gi + 4.f * h) - x) * (2.5f / 3.f) * t[i + 1];
    }
}

// ---- weight repack to fp16 [out][k] ---------------------------------------
__global__ void repack_kernel(const float* __restrict__ baseW,
                              const float* __restrict__ splineW) {
    int idx = blockIdx.x * blockDim.x + threadIdx.x;
    if (idx >= N_IN * KTOT) return;
    int o = idx / KTOT, k = idx % KTOT;
    int i = k / 9, j = k % 9;
    float v = (j == 0) ? baseW[o * N_IN + i] : splineW[o * (N_IN * 8) + i * 8 + (j - 1)];
    g_Wh[idx] = __float2half_rn(v);
}

// ---- A generation: one thread = one (row, 8-feature octet) ----------------
__global__ __launch_bounds__(256)
void gen_kernel(const float* __restrict__ x) {
    int idx = blockIdx.x * blockDim.x + threadIdx.x;   // 0 .. 32768*32-1
    int row = idx >> 5;
    int oct = idx & 31;                                // features oct*8..+7
    const float* xp = x + (size_t)row * N_IN + oct * 8;
    float4 xa = *reinterpret_cast<const float4*>(xp);
    float4 xb = *reinterpret_cast<const float4*>(xp + 4);
    float xv[8] = {xa.x, xa.y, xa.z, xa.w, xb.x, xb.y, xb.z, xb.w};
    uint32_t pk[36];
#pragma unroll
    for (int i = 0; i < 36; i++) pk[i] = 0u;
#pragma unroll
    for (int f = 0; f < 8; f++) {
        float v = xv[f];
        float sil = v / (1.f + __expf(-v));
        float bs[8];
        compute_bases(v, bs);
        unsigned short hh[9];
        hh[0] = __half_as_ushort(__float2half_rn(sil));
#pragma unroll
        for (int j = 0; j < 8; j++) hh[j + 1] = __half_as_ushort(__float2half_rn(bs[j]));
#pragma unroll
        for (int j = 0; j < 9; j++) {
            int pos = 9 * f + j;
            pk[pos >> 1] |= (uint32_t)hh[j] << ((pos & 1) * 16);
        }
    }
    unsigned char* dst = reinterpret_cast<unsigned char*>(g_A)
                       + (size_t)row * (KTOT * 2) + oct * 144;
#pragma unroll
    for (int q = 0; q < 9; q++) {
        uint4 v = make_uint4(pk[4 * q], pk[4 * q + 1], pk[4 * q + 2], pk[4 * q + 3]);
        *reinterpret_cast<uint4*>(dst + q * 16) = v;
    }
}

// ---- pure GEMM kernel ------------------------------------------------------
__global__ __launch_bounds__(256, 1)
void gemm_kernel(float* __restrict__ out) {
    extern __shared__ __align__(128) unsigned char dsm[];   // A0 A1 B0 B1
    const uint32_t sb = smem_u32(dsm);
    const int tid = threadIdx.x, wid = tid >> 5, lane = tid & 31;
    const int row0 = blockIdx.x * 128;
    const int ct   = blockIdx.y;              // output col tile (0/1)

    // warp tiling: 2 (m) x 4 (n); warp tile 64 rows x 32 cols
    const int wm = wid & 1;
    const int wn = wid >> 1;
    const uint32_t a_off = (uint32_t)(wm * 64 + (lane & 15)) * ROWB + ((lane >> 4) << 3) * 2;
    const uint32_t b_off = (uint32_t)(wn * 32 + ((lane >> 4) << 3) + (lane & 7)) * ROWB
                         + (((lane >> 3) & 1) << 3) * 2;

    float C[4][4][4];
#pragma unroll
    for (int a = 0; a < 4; a++)
#pragma unroll
        for (int b = 0; b < 4; b++)
#pragma unroll
            for (int c = 0; c < 4; c++) C[a][b][c] = 0.f;

    // stage chunk c's A and B tiles into buffer `buf` (one commit group)
    auto stage = [&](int c, int buf) {
        // A: 128 rows x 18 segs of 16B
        const unsigned char* asrc = reinterpret_cast<const unsigned char*>(g_A)
                                  + (size_t)row0 * (KTOT * 2) + c * (CK * 2);
        uint32_t adst = sb + (uint32_t)buf * TBUF;
#pragma unroll
        for (int s = 0; s < 9; s++) {
            int e = tid + 256 * s;
            int n = e / 18, seg = e % 18;
            cp16(adst + (uint32_t)n * ROWB + seg * 16,
                 asrc + (size_t)n * (KTOT * 2) + seg * 16);
        }
        // B: 128 rows x 18 segs of 16B
        const __half* bsrc = g_Wh + (size_t)(ct * 128) * KTOT + c * CK;
        uint32_t bdst = sb + (uint32_t)(2 + buf) * TBUF;
#pragma unroll
        for (int s = 0; s < 9; s++) {
            int e = tid + 256 * s;
            int n = e / 18, seg = e % 18;
            cp16(bdst + (uint32_t)n * ROWB + seg * 16,
                 bsrc + (size_t)n * KTOT + seg * 8);
        }
        cp_commit();
    };

    // prologue
    stage(0, 0);
    stage(1, 1);
    cp_wait<1>();
    __syncthreads();

    for (int c = 0; c < CHUNKS; c++) {
        const int buf = c & 1;
        const uint32_t abase = sb + (uint32_t)buf * TBUF;
        const uint32_t bbase = sb + (uint32_t)(2 + buf) * TBUF;

#pragma unroll
        for (int s = 0; s < KSTEPS; s++) {
            const uint32_t kb = (uint32_t)(s * 16) * 2;
            uint32_t A[4][4], B[2][4];
#pragma unroll
            for (int mt = 0; mt < 4; mt++)
                ldm_x4(A[mt][0], A[mt][1], A[mt][2], A[mt][3],
                       abase + a_off + (uint32_t)mt * (16 * ROWB) + kb);
#pragma unroll
            for (int nt = 0; nt < 2; nt++)
                ldm_x4(B[nt][0], B[nt][1], B[nt][2], B[nt][3],
                       bbase + b_off + (uint32_t)nt * (16 * ROWB) + kb);
#pragma unroll
            for (int mt = 0; mt < 4; mt++)
#pragma unroll
                for (int nt = 0; nt < 2; nt++) {
                    mma16816(C[mt][2 * nt][0], C[mt][2 * nt][1],
                             C[mt][2 * nt][2], C[mt][2 * nt][3],
                             A[mt][0], A[mt][1], A[mt][2], A[mt][3],
                             B[nt][0], B[nt][1]);
                    mma16816(C[mt][2 * nt + 1][0], C[mt][2 * nt + 1][1],
                             C[mt][2 * nt + 1][2], C[mt][2 * nt + 1][3],
                             A[mt][0], A[mt][1], A[mt][2], A[mt][3],
                             B[nt][2], B[nt][3]);
                }
        }

        __syncthreads();                       // reads of buf done
        if (c + 2 < CHUNKS) {
            stage(c + 2, buf);                 // refill the buffer just freed
            cp_wait<1>();                      // chunk c+1's group resident
        } else {
            cp_wait<0>();
        }
        __syncthreads();
    }

    // epilogue
    const int crow = lane >> 2, ccol = (lane & 3) * 2;
#pragma unroll
    for (int mt = 0; mt < 4; mt++) {
        int r = row0 + wm * 64 + mt * 16 + crow;
#pragma unroll
        for (int nt8 = 0; nt8 < 4; nt8++) {
            int cc = ct * 128 + wn * 32 + nt8 * 8 + ccol;
            *reinterpret_cast<float2*>(out + (size_t)r * 256 + cc) =
                make_float2(C[mt][nt8][0], C[mt][nt8][1]);
            *reinterpret_cast<float2*>(out + (size_t)(r + 8) * 256 + cc) =
                make_float2(C[mt][nt8][2], C[mt][nt8][3]);
        }
    }
}

// ---- launch ---------------------------------------------------------------
extern "C" void kernel_launch(void* const* d_in, const int* in_sizes, int n_in,
                              void* d_out, int out_size) {
    const float* x       = (const float*)d_in[0];
    const float* baseW   = (const float*)d_in[1];
    const float* splineW = (const float*)d_in[2];
    float* out           = (float*)d_out;
    const int n_rows = in_sizes[0] / N_IN;            // 32768

    repack_kernel<<<(N_IN * KTOT + 255) / 256, 256>>>(baseW, splineW);
    gen_kernel<<<(n_rows * 32) / 256, 256>>>(x);

    cudaFuncSetAttribute(gemm_kernel, cudaFuncAttributeMaxDynamicSharedMemorySize, DYN_SMEM);
    dim3 grid(n_rows / 128, 2);
    gemm_kernel<<<grid, 256, DYN_SMEM>>>(out);
}

// round 14
// speedup vs baseline: 5.8779x; 1.0457x over previous
#include <cuda_runtime.h>
#include <cuda_fp16.h>
#include <stdint.h>

// Two-kernel split (r12 win: 236us), GEMM now tuned for 2 CTAs/SM:
//  1) gen_kernel: x -> A fp16 [32768, 2304] (silu + Cox-de-Boor bases).
//  2) gemm_kernel: out = A * Wt^T. CTA tile 64x128, 256 thr, 8 warps of
//     32x32 tiles. A SINGLE-buffered + B DOUBLE-buffered = 97280 B dynamic
//     smem -> 2 CTAs/SM. The co-resident CTA hides each CTA's A-refill and
//     cp.async waits -- the exposure that capped r12's GEMM at ~35% tensor
//     utilization.
//
// K layout: k = 9*i + j; j=0: silu(x_i), j=1..8: cubic B-spline bases.
// Chunk: 16 features = 144 k = 9 k16 steps. 304-B smem row stride
// (76 words, 12 mod 32 -> ldmatrix/STS conflict-free).

#define N_IN   256
#define KTOT   2304
#define CHUNKS 16
#define CK     144
#define KSTEPS 9
#define ROWB   304
#define ABUF   (64 * ROWB)             // 19456
#define BBUF   (128 * ROWB)            // 38912
#define DYN_SMEM (ABUF + 2 * BBUF)     // 97280 -> 2 CTAs/SM
#define NROWS  32768

__device__ __align__(128) __half g_Wh[N_IN * KTOT];          // [out][k]
__device__ __align__(128) __half g_A[(size_t)NROWS * KTOT];  // [row][k] scratch

// ---- helpers --------------------------------------------------------------
__device__ __forceinline__ uint32_t smem_u32(const void* p) {
    uint32_t a;
    asm("{ .reg .u64 t; cvta.to.shared.u64 t, %1; cvt.u32.u64 %0, t; }" : "=r"(a) : "l"(p));
    return a;
}
__device__ __forceinline__ void cp16(uint32_t dst, const void* src) {
    asm volatile("cp.async.cg.shared.global [%0], [%1], 16;" :: "r"(dst), "l"(src) : "memory");
}
__device__ __forceinline__ void cp_commit() {
    asm volatile("cp.async.commit_group;" ::: "memory");
}
template <int N>
__device__ __forceinline__ void cp_wait() {
    asm volatile("cp.async.wait_group %0;" :: "n"(N) : "memory");
}
__device__ __forceinline__ void ldm_x4(uint32_t& r0, uint32_t& r1, uint32_t& r2, uint32_t& r3,
                                       uint32_t addr) {
    asm volatile("ldmatrix.sync.aligned.m8n8.x4.shared.b16 {%0,%1,%2,%3}, [%4];"
                 : "=r"(r0), "=r"(r1), "=r"(r2), "=r"(r3) : "r"(addr));
}
__device__ __forceinline__ void mma16816(float& c0, float& c1, float& c2, float& c3,
                                         uint32_t a0, uint32_t a1, uint32_t a2, uint32_t a3,
                                         uint32_t b0, uint32_t b1) {
    asm volatile(
        "mma.sync.aligned.m16n8k16.row.col.f32.f16.f16.f32 "
        "{%0,%1,%2,%3}, {%4,%5,%6,%7}, {%8,%9}, {%0,%1,%2,%3};"
        : "+f"(c0), "+f"(c1), "+f"(c2), "+f"(c3)
        : "r"(a0), "r"(a1), "r"(a2), "r"(a3), "r"(b0), "r"(b1));
}

// ---- cubic B-spline bases on grid -2.2 + 0.4j (Cox-de-Boor) ---------------
__device__ __forceinline__ void compute_bases(float x, float b[8]) {
    const float h = 0.4f;
    float t[11];
#pragma unroll
    for (int i = 0; i < 11; i++) {
        float gl = -2.2f + i * h;
        t[i] = (x >= gl && x < gl + h) ? 1.0f : 0.0f;
    }
#pragma unroll
    for (int i = 0; i < 10; i++) {
        float gi = -2.2f + i * h;
        t[i] = (x - gi) * 2.5f * t[i] + ((gi + 2.f * h) - x) * 2.5f * t[i + 1];
    }
#pragma unroll
    for (int i = 0; i < 9; i++) {
        float gi = -2.2f + i * h;
        t[i] = (x - gi) * 1.25f * t[i] + ((gi + 3.f * h) - x) * 1.25f * t[i + 1];
    }
#pragma unroll
    for (int i = 0; i < 8; i++) {
        float gi = -2.2f + i * h;
        b[i] = (x - gi) * (2.5f / 3.f) * t[i] + ((gi + 4.f * h) - x) * (2.5f / 3.f) * t[i + 1];
    }
}

// ---- weight repack to fp16 [out][k] ---------------------------------------
__global__ void repack_kernel(const float* __restrict__ baseW,
                              const float* __restrict__ splineW) {
    int idx = blockIdx.x * blockDim.x + threadIdx.x;
    if (idx >= N_IN * KTOT) return;
    int o = idx / KTOT, k = idx % KTOT;
    int i = k / 9, j = k % 9;
    float v = (j == 0) ? baseW[o * N_IN + i] : splineW[o * (N_IN * 8) + i * 8 + (j - 1)];
    g_Wh[idx] = __float2half_rn(v);
}

// ---- A generation: one thread = one (row, 8-feature octet) ----------------
__global__ __launch_bounds__(256)
void gen_kernel(const float* __restrict__ x) {
    int idx = blockIdx.x * blockDim.x + threadIdx.x;   // 0 .. 32768*32-1
    int row = idx >> 5;
    int oct = idx & 31;                                // features oct*8..+7
    const float* xp = x + (size_t)row * N_IN + oct * 8;
    float4 xa = *reinterpret_cast<const float4*>(xp);
    float4 xb = *reinterpret_cast<const float4*>(xp + 4);
    float xv[8] = {xa.x, xa.y, xa.z, xa.w, xb.x, xb.y, xb.z, xb.w};
    uint32_t pk[36];
#pragma unroll
    for (int i = 0; i < 36; i++) pk[i] = 0u;
#pragma unroll
    for (int f = 0; f < 8; f++) {
        float v = xv[f];
        float sil = v / (1.f + __expf(-v));
        float bs[8];
        compute_bases(v, bs);
        unsigned short hh[9];
        hh[0] = __half_as_ushort(__float2half_rn(sil));
#pragma unroll
        for (int j = 0; j < 8; j++) hh[j + 1] = __half_as_ushort(__float2half_rn(bs[j]));
#pragma unroll
        for (int j = 0; j < 9; j++) {
            int pos = 9 * f + j;
            pk[pos >> 1] |= (uint32_t)hh[j] << ((pos & 1) * 16);
        }
    }
    unsigned char* dst = reinterpret_cast<unsigned char*>(g_A)
                       + (size_t)row * (KTOT * 2) + oct * 144;
#pragma unroll
    for (int q = 0; q < 9; q++) {
        uint4 v = make_uint4(pk[4 * q], pk[4 * q + 1], pk[4 * q + 2], pk[4 * q + 3]);
        *reinterpret_cast<uint4*>(dst + q * 16) = v;
    }
}

// ---- pure GEMM kernel: 64x128 tile, 2 CTAs/SM ------------------------------
__global__ __launch_bounds__(256, 2)
void gemm_kernel(float* __restrict__ out) {
    extern __shared__ __align__(128) unsigned char dsm[];   // A | B0 | B1
    const uint32_t sb = smem_u32(dsm);
    const int tid = threadIdx.x, wid = tid >> 5, lane = tid & 31;
    const int row0 = blockIdx.x * 64;
    const int ct   = blockIdx.y;              // output col tile (0/1)

    // warp tiling: 2 (m) x 4 (n); warp tile 32 rows x 32 cols
    const int wm = wid & 1;
    const int wn = wid >> 1;
    const uint32_t a_off = (uint32_t)(wm * 32 + (lane & 15)) * ROWB + ((lane >> 4) << 3) * 2;
    const uint32_t b_off = (uint32_t)(wn * 32 + ((lane >> 4) << 3) + (lane & 7)) * ROWB
                         + (((lane >> 3) & 1) << 3) * 2;

    float C[2][4][4];                          // [mt][n8][frag]
#pragma unroll
    for (int a = 0; a < 2; a++)
#pragma unroll
        for (int b = 0; b < 4; b++)
#pragma unroll
            for (int c = 0; c < 4; c++) C[a][b][c] = 0.f;

    // A stage: 64 rows x 18 segs of 16B = 1152 segs (own commit group)
    auto stageA = [&](int c) {
        const unsigned char* asrc = reinterpret_cast<const unsigned char*>(g_A)
                                  + (size_t)row0 * (KTOT * 2) + c * (CK * 2);
#pragma unroll
        for (int s = 0; s < 5; s++) {
            int e = tid + 256 * s;
            if (e < 1152) {
                int n = e / 18, seg = e % 18;
                cp16(sb + (uint32_t)n * ROWB + seg * 16,
                     asrc + (size_t)n * (KTOT * 2) + seg * 16);
            }
        }
        cp_commit();
    };
    // B stage: 128 rows x 18 segs of 16B = 2304 segs (own commit group)
    auto stageB = [&](int c, int buf) {
        const __half* bsrc = g_Wh + (size_t)(ct * 128) * KTOT + c * CK;
        uint32_t bdst = sb + ABUF + (uint32_t)buf * BBUF;
#pragma unroll
        for (int s = 0; s < 9; s++) {
            int e = tid + 256 * s;
            int n = e / 18, seg = e % 18;
            cp16(bdst + (uint32_t)n * ROWB + seg * 16,
                 bsrc + (size_t)n * KTOT + seg * 8);
        }
        cp_commit();
    };

    // prologue: groups = {A0}, {B0}, {B1}; wait<1> -> A0,B0 done, B1 in flight
    stageA(0);
    stageB(0, 0);
    stageB(1, 1);
    cp_wait<1>();
    __syncthreads();

    for (int c = 0; c < CHUNKS; c++) {
        const int buf = c & 1;
        const uint32_t bbase = sb + ABUF + (uint32_t)buf * BBUF;

#pragma unroll
        for (int s = 0; s < KSTEPS; s++) {
            const uint32_t kb = (uint32_t)(s * 16) * 2;
            uint32_t A[2][4], B[2][4];
#pragma unroll
            for (int mt = 0; mt < 2; mt++)
                ldm_x4(A[mt][0], A[mt][1], A[mt][2], A[mt][3],
                       sb + a_off + (uint32_t)mt * (16 * ROWB) + kb);
#pragma unroll
            for (int nt = 0; nt < 2; nt++)
                ldm_x4(B[nt][0], B[nt][1], B[nt][2], B[nt][3],
                       bbase + b_off + (uint32_t)nt * (16 * ROWB) + kb);
#pragma unroll
            for (int mt = 0; mt < 2; mt++)
#pragma unroll
                for (int nt = 0; nt < 2; nt++) {
                    mma16816(C[mt][2 * nt][0], C[mt][2 * nt][1],
                             C[mt][2 * nt][2], C[mt][2 * nt][3],
                             A[mt][0], A[mt][1], A[mt][2], A[mt][3],
                             B[nt][0], B[nt][1]);
                    mma16816(C[mt][2 * nt + 1][0], C[mt][2 * nt + 1][1],
                             C[mt][2 * nt + 1][2], C[mt][2 * nt + 1][3],
                             A[mt][0], A[mt][1], A[mt][2], A[mt][3],
                             B[nt][2], B[nt][3]);
                }
        }

        __syncthreads();                       // A + B[buf] reads complete
        if (c + 1 < CHUNKS) {
            stageA(c + 1);                     // refill single A buffer
            if (c + 2 < CHUNKS) {
                stageB(c + 2, buf);            // refill freed B buffer
                cp_wait<1>();                  // A(c+1), B(c+1) resident
            } else {
                cp_wait<0>();
            }
            __syncthreads();
        }
    }

    // epilogue
    const int crow = lane >> 2, ccol = (lane & 3) * 2;
#pragma unroll
    for (int mt = 0; mt < 2; mt++) {
        int r = row0 + wm * 32 + mt * 16 + crow;
#pragma unroll
        for (int n8 = 0; n8 < 4; n8++) {
            int cc = ct * 128 + wn * 32 + n8 * 8 + ccol;
            *reinterpret_cast<float2*>(out + (size_t)r * 256 + cc) =
                make_float2(C[mt][n8][0], C[mt][n8][1]);
            *reinterpret_cast<float2*>(out + (size_t)(r + 8) * 256 + cc) =
                make_float2(C[mt][n8][2], C[mt][n8][3]);
        }
    }
}

// ---- launch ---------------------------------------------------------------
extern "C" void kernel_launch(void* const* d_in, const int* in_sizes, int n_in,
                              void* d_out, int out_size) {
    const float* x       = (const float*)d_in[0];
    const float* baseW   = (const float*)d_in[1];
    const float* splineW = (const float*)d_in[2];
    float* out           = (float*)d_out;
    const int n_rows = in_sizes[0] / N_IN;            // 32768

    repack_kernel<<<(N_IN * KTOT + 255) / 256, 256>>>(baseW, splineW);
    gen_kernel<<<(n_rows * 32) / 256, 256>>>(x);

    cudaFuncSetAttribute(gemm_kernel, cudaFuncAttributeMaxDynamicSharedMemorySize, DYN_SMEM);
    dim3 grid(n_rows / 64, 2);
    gemm_kernel<<<grid, 256, DYN_SMEM>>>(out);
}

// round 15
// speedup vs baseline: 6.1766x; 1.0508x over previous
#include <cuda_runtime.h>
#include <cuda_fp16.h>
#include <stdint.h>

// Two-kernel split (r12/r14 wins), GEMM re-tiled for smem-traffic:
//  1) gen_kernel: x -> A fp16 [32768, 2304] (silu + Cox-de-Boor bases).
//  2) gemm_kernel: out = A * Wt^T. CTA tile 128x256 (FULL N), 256 thr,
//     8 warps of 64x64 tiles. r14's 32x32 warp tiles made the GEMM
//     smem-wavefront-bound (reads ~ 1/m + 1/n per FLOP): 3.6 GB of smem
//     reads ~ 130us > 71us tensor floor. 64x64 tiles halve smem reads and
//     full-N CTAs halve B L2 traffic. MMA:ldmatrix ratio rises 2:1 -> 4:1.
//
// K layout: k = 9*i + j; j=0: silu(x_i), j=1..8: cubic B-spline bases.
// Chunk: 16 features = 144 k = 9 k16 steps. 304-B smem row stride
// (76 words, 12 mod 32 -> ldmatrix/STS conflict-free).

#define N_IN   256
#define KTOT   2304
#define CHUNKS 16
#define CK     144
#define KSTEPS 9
#define ROWB   304
#define ABUF   (128 * ROWB)            // 38912
#define BBUF   (256 * ROWB)            // 77824
#define DYN_SMEM (ABUF + 2 * BBUF)     // 194560
#define NROWS  32768

__device__ __align__(128) __half g_Wh[N_IN * KTOT];          // [out][k]
__device__ __align__(128) __half g_A[(size_t)NROWS * KTOT];  // [row][k] scratch

// ---- helpers --------------------------------------------------------------
__device__ __forceinline__ uint32_t smem_u32(const void* p) {
    uint32_t a;
    asm("{ .reg .u64 t; cvta.to.shared.u64 t, %1; cvt.u32.u64 %0, t; }" : "=r"(a) : "l"(p));
    return a;
}
__device__ __forceinline__ void cp16(uint32_t dst, const void* src) {
    asm volatile("cp.async.cg.shared.global [%0], [%1], 16;" :: "r"(dst), "l"(src) : "memory");
}
__device__ __forceinline__ void cp_commit() {
    asm volatile("cp.async.commit_group;" ::: "memory");
}
template <int N>
__device__ __forceinline__ void cp_wait() {
    asm volatile("cp.async.wait_group %0;" :: "n"(N) : "memory");
}
__device__ __forceinline__ void ldm_x4(uint32_t& r0, uint32_t& r1, uint32_t& r2, uint32_t& r3,
                                       uint32_t addr) {
    asm volatile("ldmatrix.sync.aligned.m8n8.x4.shared.b16 {%0,%1,%2,%3}, [%4];"
                 : "=r"(r0), "=r"(r1), "=r"(r2), "=r"(r3) : "r"(addr));
}
__device__ __forceinline__ void mma16816(float& c0, float& c1, float& c2, float& c3,
                                         uint32_t a0, uint32_t a1, uint32_t a2, uint32_t a3,
                                         uint32_t b0, uint32_t b1) {
    asm volatile(
        "mma.sync.aligned.m16n8k16.row.col.f32.f16.f16.f32 "
        "{%0,%1,%2,%3}, {%4,%5,%6,%7}, {%8,%9}, {%0,%1,%2,%3};"
        : "+f"(c0), "+f"(c1), "+f"(c2), "+f"(c3)
        : "r"(a0), "r"(a1), "r"(a2), "r"(a3), "r"(b0), "r"(b1));
}

// ---- cubic B-spline bases on grid -2.2 + 0.4j (Cox-de-Boor) ---------------
__device__ __forceinline__ void compute_bases(float x, float b[8]) {
    const float h = 0.4f;
    float t[11];
#pragma unroll
    for (int i = 0; i < 11; i++) {
        float gl = -2.2f + i * h;
        t[i] = (x >= gl && x < gl + h) ? 1.0f : 0.0f;
    }
#pragma unroll
    for (int i = 0; i < 10; i++) {
        float gi = -2.2f + i * h;
        t[i] = (x - gi) * 2.5f * t[i] + ((gi + 2.f * h) - x) * 2.5f * t[i + 1];
    }
#pragma unroll
    for (int i = 0; i < 9; i++) {
        float gi = -2.2f + i * h;
        t[i] = (x - gi) * 1.25f * t[i] + ((gi + 3.f * h) - x) * 1.25f * t[i + 1];
    }
#pragma unroll
    for (int i = 0; i < 8; i++) {
        float gi = -2.2f + i * h;
        b[i] = (x - gi) * (2.5f / 3.f) * t[i] + ((gi + 4.f * h) - x) * (2.5f / 3.f) * t[i + 1];
    }
}

// ---- weight repack to fp16 [out][k] ---------------------------------------
__global__ void repack_kernel(const float* __restrict__ baseW,
                              const float* __restrict__ splineW) {
    int idx = blockIdx.x * blockDim.x + threadIdx.x;
    if (idx >= N_IN * KTOT) return;
    int o = idx / KTOT, k = idx % KTOT;
    int i = k / 9, j = k % 9;
    float v = (j == 0) ? baseW[o * N_IN + i] : splineW[o * (N_IN * 8) + i * 8 + (j - 1)];
    g_Wh[idx] = __float2half_rn(v);
}

// ---- A generation: one thread = one (row, 8-feature octet) ----------------
__global__ __launch_bounds__(256)
void gen_kernel(const float* __restrict__ x) {
    int idx = blockIdx.x * blockDim.x + threadIdx.x;   // 0 .. 32768*32-1
    int row = idx >> 5;
    int oct = idx & 31;                                // features oct*8..+7
    const float* xp = x + (size_t)row * N_IN + oct * 8;
    float4 xa = *reinterpret_cast<const float4*>(xp);
    float4 xb = *reinterpret_cast<const float4*>(xp + 4);
    float xv[8] = {xa.x, xa.y, xa.z, xa.w, xb.x, xb.y, xb.z, xb.w};
    uint32_t pk[36];
#pragma unroll
    for (int i = 0; i < 36; i++) pk[i] = 0u;
#pragma unroll
    for (int f = 0; f < 8; f++) {
        float v = xv[f];
        float sil = v / (1.f + __expf(-v));
        float bs[8];
        compute_bases(v, bs);
        unsigned short hh[9];
        hh[0] = __half_as_ushort(__float2half_rn(sil));
#pragma unroll
        for (int j = 0; j < 8; j++) hh[j + 1] = __half_as_ushort(__float2half_rn(bs[j]));
#pragma unroll
        for (int j = 0; j < 9; j++) {
            int pos = 9 * f + j;
            pk[pos >> 1] |= (uint32_t)hh[j] << ((pos & 1) * 16);
        }
    }
    unsigned char* dst = reinterpret_cast<unsigned char*>(g_A)
                       + (size_t)row * (KTOT * 2) + oct * 144;
#pragma unroll
    for (int q = 0; q < 9; q++) {
        uint4 v = make_uint4(pk[4 * q], pk[4 * q + 1], pk[4 * q + 2], pk[4 * q + 3]);
        *reinterpret_cast<uint4*>(dst + q * 16) = v;
    }
}

// ---- pure GEMM kernel: 128x256 tile, 64x64 warp tiles ----------------------
__global__ __launch_bounds__(256, 1)
void gemm_kernel(float* __restrict__ out) {
    extern __shared__ __align__(128) unsigned char dsm[];   // A | B0 | B1
    const uint32_t sb = smem_u32(dsm);
    const int tid = threadIdx.x, wid = tid >> 5, lane = tid & 31;
    const int row0 = blockIdx.x * 128;

    // warp tiling: 2 (m) x 4 (n); warp tile 64 rows x 64 cols
    const int wm = wid & 1;
    const int wn = wid >> 1;
    const uint32_t a_off = (uint32_t)(wm * 64 + (lane & 15)) * ROWB + ((lane >> 4) << 3) * 2;
    const uint32_t b_off = (uint32_t)(wn * 64 + ((lane >> 4) << 3) + (lane & 7)) * ROWB
                         + (((lane >> 3) & 1) << 3) * 2;

    float C[4][8][4];                          // [mt][n8][frag] = 128 regs
#pragma unroll
    for (int a = 0; a < 4; a++)
#pragma unroll
        for (int b = 0; b < 8; b++)
#pragma unroll
            for (int c = 0; c < 4; c++) C[a][b][c] = 0.f;

    // A stage: 128 rows x 18 segs of 16B = 2304 segs (own commit group)
    auto stageA = [&](int c) {
        const unsigned char* asrc = reinterpret_cast<const unsigned char*>(g_A)
                                  + (size_t)row0 * (KTOT * 2) + c * (CK * 2);
#pragma unroll
        for (int s = 0; s < 9; s++) {
            int e = tid + 256 * s;
            int n = e / 18, seg = e % 18;
            cp16(sb + (uint32_t)n * ROWB + seg * 16,
                 asrc + (size_t)n * (KTOT * 2) + seg * 16);
        }
        cp_commit();
    };
    // B stage: 256 rows x 18 segs of 16B = 4608 segs (own commit group)
    auto stageB = [&](int c, int buf) {
        const __half* bsrc = g_Wh + c * CK;
        uint32_t bdst = sb + ABUF + (uint32_t)buf * BBUF;
#pragma unroll
        for (int s = 0; s < 18; s++) {
            int e = tid + 256 * s;
            int n = e / 18, seg = e % 18;
            cp16(bdst + (uint32_t)n * ROWB + seg * 16,
                 bsrc + (size_t)n * KTOT + seg * 8);
        }
        cp_commit();
    };

    // prologue: groups {A0}{B0}{B1}; wait<1> -> A0,B0 resident, B1 in flight
    stageA(0);
    stageB(0, 0);
    stageB(1, 1);
    cp_wait<1>();
    __syncthreads();

    for (int c = 0; c < CHUNKS; c++) {
        const int buf = c & 1;
        const uint32_t bbase = sb + ABUF + (uint32_t)buf * BBUF;

#pragma unroll
        for (int s = 0; s < KSTEPS; s++) {
            const uint32_t kb = (uint32_t)(s * 16) * 2;
            uint32_t A[4][4], B[4][4];
#pragma unroll
            for (int mt = 0; mt < 4; mt++)
                ldm_x4(A[mt][0], A[mt][1], A[mt][2], A[mt][3],
                       sb + a_off + (uint32_t)mt * (16 * ROWB) + kb);
#pragma unroll
            for (int nt = 0; nt < 4; nt++)
                ldm_x4(B[nt][0], B[nt][1], B[nt][2], B[nt][3],
                       bbase + b_off + (uint32_t)nt * (16 * ROWB) + kb);
#pragma unroll
            for (int mt = 0; mt < 4; mt++)
#pragma unroll
                for (int nt = 0; nt < 4; nt++) {
                    mma16816(C[mt][2 * nt][0], C[mt][2 * nt][1],
                             C[mt][2 * nt][2], C[mt][2 * nt][3],
                             A[mt][0], A[mt][1], A[mt][2], A[mt][3],
                             B[nt][0], B[nt][1]);
                    mma16816(C[mt][2 * nt + 1][0], C[mt][2 * nt + 1][1],
                             C[mt][2 * nt + 1][2], C[mt][2 * nt + 1][3],
                             A[mt][0], A[mt][1], A[mt][2], A[mt][3],
                             B[nt][2], B[nt][3]);
                }
        }

        __syncthreads();                       // A + B[buf] reads complete
        if (c + 1 < CHUNKS) {
            stageA(c + 1);                     // refill single A buffer
            if (c + 2 < CHUNKS) {
                stageB(c + 2, buf);            // refill freed B buffer
                cp_wait<1>();                  // A(c+1), B(c+1) resident
            } else {
                cp_wait<0>();
            }
            __syncthreads();
        }
    }

    // epilogue
    const int crow = lane >> 2, ccol = (lane & 3) * 2;
#pragma unroll
    for (int mt = 0; mt < 4; mt++) {
        int r = row0 + wm * 64 + mt * 16 + crow;
#pragma unroll
        for (int n8 = 0; n8 < 8; n8++) {
            int cc = wn * 64 + n8 * 8 + ccol;
            *reinterpret_cast<float2*>(out + (size_t)r * 256 + cc) =
                make_float2(C[mt][n8][0], C[mt][n8][1]);
            *reinterpret_cast<float2*>(out + (size_t)(r + 8) * 256 + cc) =
                make_float2(C[mt][n8][2], C[mt][n8][3]);
        }
    }
}

// ---- launch ---------------------------------------------------------------
extern "C" void kernel_launch(void* const* d_in, const int* in_sizes, int n_in,
                              void* d_out, int out_size) {
    const float* x       = (const float*)d_in[0];
    const float* baseW   = (const float*)d_in[1];
    const float* splineW = (const float*)d_in[2];
    float* out           = (float*)d_out;
    const int n_rows = in_sizes[0] / N_IN;            // 32768

    repack_kernel<<<(N_IN * KTOT + 255) / 256, 256>>>(baseW, splineW);
    gen_kernel<<<(n_rows * 32) / 256, 256>>>(x);

    cudaFuncSetAttribute(gemm_kernel, cudaFuncAttributeMaxDynamicSharedMemorySize, DYN_SMEM);
    gemm_kernel<<<n_rows / 128, 256, DYN_SMEM>>>(out);
}